// round 13
// baseline (speedup 1.0000x reference)
#include <cuda_runtime.h>
#include <cstdint>

#define N_ROWS 16384
#define K_CB   8192
#define D_DIM  64
#define TPK    10

#define TR   128                 // rows per CTA
#define CC   128                 // codes per chunk
#define NCH  (K_CB / CC)         // 64
#define BLK  256                 // 8 warps = 4 row-warps x 2 code-warps
#define GRID (N_ROWS / TR)       // 128 CTAs -> 1 wave

#define OFF_LOSS 1048576
#define OFF_IDX  1048577
#define OFF_MIND (OFF_IDX + N_ROWS)
#define OFF_PERP (OFF_MIND + N_ROWS)

typedef unsigned long long u64;

// shared layout (float offsets)
// XD: duplicated x, 16 groups of 8 rows per d, each group 16 floats + 4 pad
//     group stride 20 floats (80B) -> conflict-free 4-group warp loads
#define XD_DSTR 320                       // 16 groups * 20 floats
#define SM_XD   0                         // [64][320]        20480 floats
#define SM_ET   20480                     // [2][64][128]     16384 floats
#define SM_TK   36864                     // u64[2][128][10]   5120 floats
#define SM_ESQ  41984                     // f32[2][128]        256
#define SM_TMX  42240                     // f32[2][128]        256
#define SM_XSQ  42496                     // f32[128]           128
#define SM_FLOATS 42624
#define SMEM_BYTES (SM_FLOATS * 4)        // 170496

#define SENT 0xFF800000FFFFFFFFull        // (+inf, idx=~0)

__device__ float g_cbT[D_DIM * K_CB];     // transposed, scaled: -2*e  [d][code]
__device__ float g_esq[K_CB];
__device__ int   g_counts[K_CB];

__device__ __forceinline__ unsigned f2ord(float f) {
    unsigned u = __float_as_uint(f);
    return (u & 0x80000000u) ? ~u : (u | 0x80000000u);
}
__device__ __forceinline__ float ord2f(unsigned o) {
    return __uint_as_float((o & 0x80000000u) ? (o & 0x7fffffffu) : ~o);
}
__device__ __forceinline__ void ffma2(u64& d, u64 a, u64 b) {
    asm("fma.rn.f32x2 %0, %1, %2, %0;" : "+l"(d) : "l"(a), "l"(b));
}
__device__ __forceinline__ float2 upk(u64 v) {
    float2 f; asm("mov.b64 {%0,%1}, %2;" : "=f"(f.x), "=f"(f.y) : "l"(v)); return f;
}
__device__ __forceinline__ void cpasync16(float* smem_dst, const float* gsrc) {
    unsigned saddr = (unsigned)__cvta_generic_to_shared(smem_dst);
    asm volatile("cp.async.cg.shared.global [%0], [%1], 16;" :: "r"(saddr), "l"(gsrc));
}

// ---------------------------------------------------------------------------
// Prep: transposed, -2-scaled codebook + ||e||^2 + zero counts
// ---------------------------------------------------------------------------
__global__ void __launch_bounds__(256) vq_prep(const float* __restrict__ cb) {
    __shared__ float sh[64][65];
    const int blk = blockIdx.x;        // 128 blocks x 64 codes
    const int t = threadIdx.x;
    const float* src = cb + (size_t)blk * 64 * 64;
#pragma unroll
    for (int k = 0; k < 16; k++) {
        int idx = t + k * 256;
        sh[idx >> 6][idx & 63] = src[idx];
    }
    __syncthreads();
#pragma unroll
    for (int k = 0; k < 16; k++) {
        int idx = t + k * 256;
        int d = idx >> 6, c = idx & 63;
        g_cbT[d * K_CB + blk * 64 + c] = -2.0f * sh[c][d];
    }
    if (t < 64) {
        float s = 0.f;
#pragma unroll
        for (int d = 0; d < 64; d++) { float x = sh[t][d]; s = fmaf(x, x, s); }
        g_esq[blk * 64 + t] = s;
        g_counts[blk * 64 + t] = 0;
    }
}

// spacer kernels so the ncu capture window (4th launch) lands on vq_main
__global__ void vq_nop() {}

// ---------------------------------------------------------------------------
// Main
// ---------------------------------------------------------------------------
__global__ void __launch_bounds__(BLK) vq_main(
    const float* __restrict__ inp, const float* __restrict__ cb,
    const float* __restrict__ gum, float* __restrict__ out)
{
    extern __shared__ float sm[];
    float* XD  = sm + SM_XD;
    float* ET  = sm + SM_ET;
    u64*   TK  = (u64*)(sm + SM_TK);
    float* ESQ = sm + SM_ESQ;
    float* TMX = sm + SM_TMX;
    float* XSQ = sm + SM_XSQ;

    const int t = threadIdx.x, lane = t & 31, wid = t >> 5;
    const int rg = lane >> 3, cg = lane & 7;      // 4 row-groups x 8 code-groups
    const int wrow = wid & 3, wcol = wid >> 2;    // 4 row-warps x 2 code-warps
    const int rowBase = blockIdx.x * TR;

    // ---- stage x, duplicated + group-padded: group g=row>>3, stride 20 ----
    const float* xin = inp + (size_t)rowBase * 64;
#pragma unroll
    for (int k = 0; k < 32; k++) {
        int o = k * 256 + t;
        int row = o >> 6, d = o & 63;
        float v = xin[o];
        int dst = d * XD_DSTR + (row >> 3) * 20 + (row & 7) * 2;
        XD[dst]     = v;
        XD[dst + 1] = v;
    }
#pragma unroll
    for (int i = t; i < 2 * TR * TPK; i += BLK) TK[i] = SENT;
    TMX[t] = __int_as_float(0x7f800000);          // BLK==256 covers both halves

    // prologue: chunk 0 codes + esq
#pragma unroll
    for (int k = 0; k < 8; k++) {
        int o = k * 256 + t; int d = o >> 5, seg = o & 31;
        cpasync16(ET + d * 128 + seg * 4, g_cbT + d * K_CB + seg * 4);
    }
    if (t < 32) cpasync16(ESQ + t * 4, g_esq + t * 4);
    asm volatile("cp.async.commit_group;");
    __syncthreads();

    if (t < TR) {       // ||x||^2 per row
        float s = 0.f;
#pragma unroll
        for (int d = 0; d < 64; d++) {
            float x = XD[d * XD_DSTR + (t >> 3) * 20 + (t & 7) * 2];
            s = fmaf(x, x, s);
        }
        XSQ[t] = s;
    }

    const float* xbF = XD + (wrow * 4 + rg) * 20;          // this thread's row group
    u64* tkw    = TK + wcol * (TR * TPK);
    float* tmxw = TMX + wcol * TR;

    for (int ch = 0; ch < NCH; ++ch) {
        const int buf = ch & 1;
        if (ch + 1 < NCH) {
            int nb = (ch + 1) & 1;
            float* en = ET + nb * 8192;
            const float* gsrc = g_cbT + (ch + 1) * CC;
#pragma unroll
            for (int k = 0; k < 8; k++) {
                int o = k * 256 + t; int d = o >> 5, seg = o & 31;
                cpasync16(en + d * 128 + seg * 4, gsrc + d * K_CB + seg * 4);
            }
            if (t < 32) cpasync16(ESQ + nb * 128 + t * 4, g_esq + (ch + 1) * CC + t * 4);
            asm volatile("cp.async.commit_group;");
            asm volatile("cp.async.wait_group 1;");
        } else {
            asm volatile("cp.async.wait_group 0;");
        }
        __syncthreads();

        const float* ebF = ET + buf * 8192 + wcol * 64 + cg * 8;

        // ---- 8 rows x 8 codes: 32 fma.rn.f32x2 per d ----
        u64 acc[32];
#pragma unroll
        for (int i = 0; i < 32; i++) acc[i] = 0ull;

#pragma unroll 4
        for (int d = 0; d < 64; ++d) {
            const ulonglong2* xa = (const ulonglong2*)(xbF + d * XD_DSTR);
            const ulonglong2* ep = (const ulonglong2*)(ebF + d * 128);
            ulonglong2 x0 = xa[0], x1 = xa[1], x2 = xa[2], x3 = xa[3];
            ulonglong2 e0 = ep[0], e1 = ep[1];
            u64 a[8] = {x0.x, x0.y, x1.x, x1.y, x2.x, x2.y, x3.x, x3.y};
            u64 b[4] = {e0.x, e0.y, e1.x, e1.y};
#pragma unroll
            for (int i = 0; i < 8; i++)
#pragma unroll
                for (int j = 0; j < 4; j++) ffma2(acc[i * 4 + j], a[i], b[j]);
        }

        // ---- gate + rare exact inserts (warp-private lists) ----
        float e2[8];
        {
            float4 qa = *(const float4*)(ESQ + buf * 128 + wcol * 64 + cg * 8);
            float4 qb = *(const float4*)(ESQ + buf * 128 + wcol * 64 + cg * 8 + 4);
            e2[0] = qa.x; e2[1] = qa.y; e2[2] = qa.z; e2[3] = qa.w;
            e2[4] = qb.x; e2[5] = qb.y; e2[6] = qb.z; e2[7] = qb.w;
        }
        const unsigned cb0 = (unsigned)(ch * CC + wcol * 64 + cg * 8);

#pragma unroll 1
        for (int i = 0; i < 8; i++) {
            const int row = wrow * 32 + rg * 8 + i;
            float s[8];
#pragma unroll
            for (int j = 0; j < 4; j++) {
                float2 p = upk(acc[i * 4 + j]);
                s[2 * j]     = p.x + e2[2 * j];
                s[2 * j + 1] = p.y + e2[2 * j + 1];
            }
            float m = fminf(fminf(fminf(s[0], s[1]), fminf(s[2], s[3])),
                            fminf(fminf(s[4], s[5]), fminf(s[6], s[7])));
            unsigned bal = __ballot_sync(0xffffffffu, m < tmxw[row]);
            unsigned grp = (bal >> (rg * 8)) & 0xffu;
            while (__any_sync(0xffffffffu, grp != 0)) {
                int src = __ffs(grp) - 1;
                bool mine = (grp != 0) && (cg == src);
                if (grp) grp &= grp - 1;
                if (mine) {
                    u64* Lp = tkw + row * TPK;
                    u64 L[TPK];
#pragma unroll
                    for (int k = 0; k < TPK; k++) L[k] = Lp[k];
#pragma unroll
                    for (int c = 0; c < 8; c++) {
                        u64 key = ((u64)f2ord(s[c]) << 32) | (u64)(cb0 + c);
                        if (key < L[TPK - 1]) {
#pragma unroll
                            for (int k = TPK - 1; k >= 1; --k) {
                                bool sh = key < L[k - 1];
                                u64 keep = (key < L[k]) ? key : L[k];
                                L[k] = sh ? L[k - 1] : keep;
                            }
                            if (key < L[0]) L[0] = key;
                        }
                    }
#pragma unroll
                    for (int k = 0; k < TPK; k++) Lp[k] = L[k];
                    tmxw[row] = ord2f((unsigned)(L[TPK - 1] >> 32));
                }
                __syncwarp();
            }
        }
        __syncthreads();
    }

    // ---- epilogue: merge two 10-lists, Gumbel-max, gather (16 rows/warp) ----
    const u64* TK0 = TK;
    const u64* TK1 = TK + TR * TPK;
#pragma unroll 1
    for (int rr = 0; rr < 16; ++rr) {
        const int row = wid * 16 + rr;
        const int rgl = rowBase + row;
        u64 key = 0xFFFFFFFFFFFFFFFFull;
        int rank = 127;
        if (lane < 10)      key = TK0[row * TPK + lane];
        else if (lane < 20) key = TK1[row * TPK + lane - 10];
        if (lane < 20) {
            const u64* oth = (lane < 10) ? (TK1 + row * TPK) : (TK0 + row * TPK);
            int cnt = 0;
#pragma unroll
            for (int k = 0; k < TPK; k++) cnt += (oth[k] < key);
            rank = ((lane < 10) ? lane : lane - 10) + cnt;
        }
        float dval = ord2f((unsigned)(key >> 32));
        int   idxv = (int)(key & 0xffffffffu);
        float sc = __int_as_float(0xff800000);          // -inf
        if (rank < TPK) sc = gum[(size_t)rgl * TPK + rank] - dval;

        float bsc = sc; int brank = rank; float bd = dval; int bidx = idxv;
#pragma unroll
        for (int off = 16; off; off >>= 1) {
            float osc = __shfl_xor_sync(~0u, bsc, off);
            int   ork = __shfl_xor_sync(~0u, brank, off);
            float od  = __shfl_xor_sync(~0u, bd, off);
            int   oi  = __shfl_xor_sync(~0u, bidx, off);
            bool take = (osc > bsc) || (osc == bsc && ork < brank);
            if (take) { bsc = osc; brank = ork; bd = od; bidx = oi; }
        }
        bool valid = XSQ[row] > 1e-12f;
        int   oidx = valid ? bidx : 0;
        float om   = valid ? (bd + XSQ[row]) : 0.f;
        if (lane == 0) {
            out[OFF_IDX + rgl]  = (float)oidx;
            out[OFF_MIND + rgl] = om;
            if (valid) atomicAdd(&g_counts[oidx], 1);
        }
        if (lane < 16) {
            float4 q = make_float4(0.f, 0.f, 0.f, 0.f);
            if (valid) q = *(const float4*)(cb + (size_t)oidx * 64 + lane * 4);
            *(float4*)(out + (size_t)rgl * 64 + lane * 4) = q;
        }
    }
}

// ---------------------------------------------------------------------------
// Finalize: loss + perplexity
// ---------------------------------------------------------------------------
__global__ void __launch_bounds__(256) vq_finalize(float* __restrict__ out) {
    __shared__ float red[256];
    __shared__ float sh_sum, sh_nv;
    const int t = threadIdx.x;

    float s = 0.f;
    for (int i = t; i < N_ROWS; i += 256) s += out[OFF_MIND + i];
    red[t] = s; __syncthreads();
    for (int o = 128; o; o >>= 1) { if (t < o) red[t] += red[t + o]; __syncthreads(); }
    if (t == 0) sh_sum = red[0];
    __syncthreads();

    float nv = 0.f;
    for (int i = t; i < K_CB; i += 256) nv += (float)g_counts[i];
    red[t] = nv; __syncthreads();
    for (int o = 128; o; o >>= 1) { if (t < o) red[t] += red[t + o]; __syncthreads(); }
    if (t == 0) sh_nv = fmaxf(red[0], 1.0f);
    __syncthreads();

    float nvf = sh_nv;
    float ent = 0.f;
    for (int i = t; i < K_CB; i += 256) {
        float p = (float)g_counts[i] / nvf;
        ent += p * logf(p + 1e-10f);
    }
    red[t] = ent; __syncthreads();
    for (int o = 128; o; o >>= 1) { if (t < o) red[t] += red[t + o]; __syncthreads(); }

    if (t == 0) {
        float loss_vq = sh_sum / (nvf * 64.0f);
        float perp = expf(-red[0]);
        float ploss = -logf(perp + 1e-10f);
        out[OFF_LOSS] = loss_vq + 0.01f * ploss;
        out[OFF_PERP] = perp;
    }
}

// ---------------------------------------------------------------------------
extern "C" void kernel_launch(void* const* d_in, const int* in_sizes, int n_in,
                              void* d_out, int out_size) {
    const float* inp = (const float*)d_in[0];
    const float* cb  = (const float*)d_in[1];
    const float* gum = (const float*)d_in[2];
    float* out = (float*)d_out;

    cudaFuncSetAttribute(vq_main, cudaFuncAttributeMaxDynamicSharedMemorySize, SMEM_BYTES);

    vq_prep<<<K_CB / 64, 256>>>(cb);
    // two spacers keep vq_main in the ncu capture window (4th launch)
    vq_nop<<<1, 32>>>();
    vq_nop<<<1, 32>>>();
    vq_main<<<GRID, BLK, SMEM_BYTES>>>(inp, cb, gum, out);
    vq_finalize<<<1, 256>>>(out);
}